// round 17
// baseline (speedup 1.0000x reference)
#include <cuda_runtime.h>
#include <cuda_fp16.h>
#include <mma.h>
#include <cstdint>
#include <cstddef>

using namespace nvcuda;

#define B_ 64
#define S_ 2048
#define E_ 512
#define C_ 512
#define H_ 256

// ---------------- scratch (static device globals; no allocation) ----------------
__device__ float g_ctx[B_ * H_];             // ctx_feat + b_ctx + b_word  [B,H]
__device__ float g_scores[B_ * S_];          // pre-softmax scores         [B,S]
__device__ float4 g_tpart4[B_ * 16 * 128];   // per-tile weighted partials [B,16,E/4]
__device__ float g_mt[B_ * 16];              // per-tile score max
__device__ float g_lt[B_ * 16];              // per-tile exp-sum
__device__ unsigned g_ticket;                // persistent-CTA work queue
__device__ unsigned g_ctx_done;              // == N_CTX_T when ctx finished
__device__ unsigned g_bdone[B_];             // per-batch completed valid tiles
__device__ unsigned g_done;                  // CTA exit counter (self-reset)

#define LDH 40                 // smem leading dim in halves (80B, 16B multiple)
#define A_HL (128 * LDH)
#define B_HL (256 * LDH)
#define LDWF 132
#define N_CTX_T 32u
#define N_TICKETS (N_CTX_T + 1024u)
#define GRID_CTAS 152

// ---------------------------------------------------------------------------
// Single mega kernel. Persistent CTAs over an atomic ticket queue:
//   tickets [0,32):   ctx slices (g_ctx = b_ctx + b_word + context @ W_ctx^T)
//   tickets [32,1056): score tiles (b, s-tile of 128):
//     fp16 wmma GEMM 128x256xK512 (double-buffered, reg-prefetched)
//     -> tanh.approx -> dot(w_hidden) -> scores
//     -> tile softmax stats (m_t, L_t) + weighted partial sum_r w_r*A[r,:]
//        (A rows re-read from hot L2; next tile's chunk-0 LDGs issued first
//         so their latency hides under the wsum loop)
//     -> last tile of batch b combines all tiles: feat + attn (in-kernel
//        "finalize", overlapped with other CTAs' GEMM work)
// Last exiting CTA resets all counters (graph-replay safe).
// ---------------------------------------------------------------------------
__global__ __launch_bounds__(512, 1) void mega_kernel(
    const float* __restrict__ A,         // [B,S,E]
    const float* __restrict__ Ww,        // W_word [H,E]
    const int* __restrict__ lengths,
    const float* __restrict__ w_hidden,
    const float* __restrict__ context,   // [B,C]
    const float* __restrict__ W_ctx,     // [H,C]
    const float* __restrict__ b_ctx,
    const float* __restrict__ b_word,
    float* __restrict__ feat,            // [B,E]
    float* __restrict__ attn_out) {      // [B,S] or nullptr
    extern __shared__ __align__(128) char smc[];
    __half* As0 = reinterpret_cast<__half*>(smc);                 // [2][A_HL]
    __half* Bs0 = reinterpret_cast<__half*>(smc + 2 * A_HL * 2);  // [2][B_HL]
    float* epif = reinterpret_cast<float*>(smc);                  // epilogue 128xLDWF
    float* ctx_s = reinterpret_cast<float*>(smc + 128 * LDWF * 4);
    float* wh_s = ctx_s + 256;
    __shared__ unsigned s_tile;
    __shared__ unsigned s_old;
    __shared__ float row_sc[128];
    __shared__ float wrow[128];
    __shared__ float s_aux;
    __shared__ float sE[16];
    __shared__ float sM, sInv;

    int tid = threadIdx.x;
    int lane = tid & 31, wid = tid >> 5;
    int wm = wid & 3, wn = wid >> 2;

    if (tid < 256) wh_s[tid] = w_hidden[tid];  // loop-invariant

    // per-thread staging slots (K=32 chunk): A 2 x float4, B 4 x float4
    int ar[2], ac[2], br[4], bc[4];
#pragma unroll
    for (int i = 0; i < 2; i++) {
        int idx = tid + i * 512;
        ar[i] = idx >> 3;
        ac[i] = (idx & 7) * 4;
    }
#pragma unroll
    for (int i = 0; i < 4; i++) {
        int idx = tid + i * 512;
        br[i] = idx >> 3;
        bc[i] = (idx & 7) * 4;
    }

    float4 ra[2], rb[4];
    bool pre = false;

    if (tid == 0) s_tile = atomicAdd(&g_ticket, 1u);
    __syncthreads();
    unsigned t = s_tile;

    while (t < N_TICKETS) {
        if (t < N_CTX_T) {
            // ---------------- ctx ticket: 512 h-dot-products ----------------
            int idx = (int)t * 512 + tid;
            int cb = idx >> 8, h = idx & 255;
            const float4* wr = reinterpret_cast<const float4*>(W_ctx + (size_t)h * C_);
            const float4* cr = reinterpret_cast<const float4*>(context + (size_t)cb * C_);
            float acc = b_ctx[h] + b_word[h];
#pragma unroll 8
            for (int i = 0; i < C_ / 4; i++) {
                float4 w = wr[i];
                float4 c = cr[i];
                acc += w.x * c.x + w.y * c.y + w.z * c.z + w.w * c.w;
            }
            g_ctx[cb * H_ + h] = acc;
            __threadfence();
            __syncthreads();
            if (tid == 0) {
                atomicAdd(&g_ctx_done, 1u);
                s_tile = atomicAdd(&g_ticket, 1u);
            }
            pre = false;
            __syncthreads();
            t = s_tile;
            continue;
        }

        unsigned st = t - N_CTX_T;
        int b = (int)(st >> 4);
        int tile = (int)(st & 15u);
        int s0 = tile * 128;
        int len = lengths[b];
        if (s0 >= len) {
            if (tid == 0) s_tile = atomicAdd(&g_ticket, 1u);
            pre = false;
            __syncthreads();
            t = s_tile;
            continue;
        }
        int nv = len - s0;
        nv = (nv > 128) ? 128 : nv;
        const float* Ab = A + ((size_t)b * S_ + s0) * E_;

        if (!pre) {  // chunk-0 prefetch (skipped if issued during prev wsum)
#pragma unroll
            for (int i = 0; i < 2; i++)
                ra[i] = *reinterpret_cast<const float4*>(Ab + (size_t)ar[i] * E_ + ac[i]);
#pragma unroll
            for (int i = 0; i < 4; i++)
                rb[i] = *reinterpret_cast<const float4*>(Ww + (size_t)br[i] * E_ + bc[i]);
        }
        pre = false;

        // ---------------- GEMM: 16 double-buffered K=32 chunks ----------------
        wmma::fragment<wmma::accumulator, 16, 16, 16, float> acc[2][4];
#pragma unroll
        for (int mi = 0; mi < 2; mi++)
#pragma unroll
            for (int ni = 0; ni < 4; ni++) wmma::fill_fragment(acc[mi][ni], 0.0f);

        for (int kc = 0; kc < 16; kc++) {
            int buf = kc & 1;
            __half* Asb = As0 + buf * A_HL;
            __half* Bsb = Bs0 + buf * B_HL;
#pragma unroll
            for (int i = 0; i < 2; i++) {
                __half2 p0 = __floats2half2_rn(ra[i].x, ra[i].y);
                __half2 p1 = __floats2half2_rn(ra[i].z, ra[i].w);
                uint2 u = make_uint2(*reinterpret_cast<uint32_t*>(&p0),
                                     *reinterpret_cast<uint32_t*>(&p1));
                *reinterpret_cast<uint2*>(&Asb[ar[i] * LDH + ac[i]]) = u;
            }
#pragma unroll
            for (int i = 0; i < 4; i++) {
                __half2 p0 = __floats2half2_rn(rb[i].x, rb[i].y);
                __half2 p1 = __floats2half2_rn(rb[i].z, rb[i].w);
                uint2 u = make_uint2(*reinterpret_cast<uint32_t*>(&p0),
                                     *reinterpret_cast<uint32_t*>(&p1));
                *reinterpret_cast<uint2*>(&Bsb[br[i] * LDH + bc[i]]) = u;
            }
            __syncthreads();
            if (kc + 1 < 16) {  // prefetch next chunk; hides under mma below
                int k0 = (kc + 1) * 32;
#pragma unroll
                for (int i = 0; i < 2; i++)
                    ra[i] = *reinterpret_cast<const float4*>(Ab + (size_t)ar[i] * E_ +
                                                             k0 + ac[i]);
#pragma unroll
                for (int i = 0; i < 4; i++)
                    rb[i] = *reinterpret_cast<const float4*>(Ww + (size_t)br[i] * E_ +
                                                             k0 + bc[i]);
            }
            const __half* As = As0 + buf * A_HL;
            const __half* Bs = Bs0 + buf * B_HL;
#pragma unroll
            for (int kk = 0; kk < 2; kk++) {
                int ko = kk * 16;
                wmma::fragment<wmma::matrix_a, 16, 16, 16, __half, wmma::row_major> af[2];
                wmma::load_matrix_sync(af[0], As + (wm * 32) * LDH + ko, LDH);
                wmma::load_matrix_sync(af[1], As + (wm * 32 + 16) * LDH + ko, LDH);
#pragma unroll
                for (int ni = 0; ni < 4; ni++) {
                    wmma::fragment<wmma::matrix_b, 16, 16, 16, __half, wmma::col_major> bf;
                    wmma::load_matrix_sync(bf, Bs + (wn * 64 + ni * 16) * LDH + ko, LDH);
                    wmma::mma_sync(acc[0][ni], af[0], bf, acc[0][ni]);
                    wmma::mma_sync(acc[1][ni], af[1], bf, acc[1][ni]);
                }
            }
        }

        // ---- ctx is long done by now; spin once, stage it ----
        if (tid == 0) {
            while (atomicAdd(&g_ctx_done, 0u) < N_CTX_T) {}
            __threadfence();
        }
        __syncthreads();
        if (tid < 256) ctx_s[tid] = g_ctx[b * H_ + tid];

        // ---- epilogue: tanh.approx + dot(w_hidden) -> row scores ----
        float psum[8];
#pragma unroll
        for (int rr = 0; rr < 8; rr++) psum[rr] = 0.0f;

#pragma unroll
        for (int hh = 0; hh < 2; hh++) {
            __syncthreads();
            if ((wn >> 1) == hh) {
                int cw = (wn & 1) * 64;
#pragma unroll
                for (int mi = 0; mi < 2; mi++)
#pragma unroll
                    for (int ni = 0; ni < 4; ni++)
                        wmma::store_matrix_sync(
                            epif + (wm * 32 + mi * 16) * LDWF + cw + ni * 16,
                            acc[mi][ni], LDWF, wmma::mem_row_major);
            }
            __syncthreads();
#pragma unroll
            for (int rr = 0; rr < 8; rr++) {
                int r = wid * 8 + rr;
#pragma unroll
                for (int j = 0; j < 4; j++) {
                    int c = lane + j * 32;
                    float x = epif[r * LDWF + c] + ctx_s[hh * 128 + c];
                    float th;
                    asm("tanh.approx.f32 %0, %1;" : "=f"(th) : "f"(x));
                    psum[rr] += th * wh_s[hh * 128 + c];
                }
            }
        }
#pragma unroll
        for (int rr = 0; rr < 8; rr++) {
            float s = psum[rr];
#pragma unroll
            for (int o = 16; o > 0; o >>= 1) s += __shfl_xor_sync(0xffffffffu, s, o);
            if (lane == 0) {
                int r = wid * 8 + rr;
                g_scores[(size_t)b * S_ + s0 + r] = s;
                row_sc[r] = s;
            }
        }
        __syncthreads();

        // ---- tile softmax stats: m_t, weights, L_t ----
        if (wid == 0) {
            float m = -1e30f;
#pragma unroll
            for (int k = 0; k < 4; k++) {
                int r = lane + k * 32;
                float v = (r < nv) ? row_sc[r] : -1e30f;
                m = fmaxf(m, v);
            }
#pragma unroll
            for (int o = 16; o > 0; o >>= 1)
                m = fmaxf(m, __shfl_xor_sync(0xffffffffu, m, o));
            if (lane == 0) s_aux = m;
        }
        __syncthreads();
        float mt = s_aux;
        if (tid < 128) wrow[tid] = (tid < nv) ? __expf(row_sc[tid] - mt) : 0.0f;
        __syncthreads();
        if (wid == 0) {
            float L = 0.0f;
#pragma unroll
            for (int k = 0; k < 4; k++) L += wrow[lane + k * 32];
#pragma unroll
            for (int o = 16; o > 0; o >>= 1) L += __shfl_xor_sync(0xffffffffu, L, o);
            if (lane == 0) {
                g_mt[b * 16 + tile] = mt;
                g_lt[b * 16 + tile] = L;
            }
        }

        // ---- acquire next ticket NOW, issue its chunk-0 prefetch so the
        //      global-load latency hides under the wsum loop below ----
        if (tid == 0) s_tile = atomicAdd(&g_ticket, 1u);
        __syncthreads();  // s_tile + wrow + g_mt/g_lt visible
        unsigned tn = s_tile;
        if (tn >= N_CTX_T && tn < N_TICKETS) {
            unsigned st2 = tn - N_CTX_T;
            int b2 = (int)(st2 >> 4);
            int s02 = (int)(st2 & 15u) * 128;
            if (s02 < lengths[b2]) {
                const float* Ab2 = A + ((size_t)b2 * S_ + s02) * E_;
#pragma unroll
                for (int i = 0; i < 2; i++)
                    ra[i] = *reinterpret_cast<const float4*>(Ab2 + (size_t)ar[i] * E_ + ac[i]);
#pragma unroll
                for (int i = 0; i < 4; i++)
                    rb[i] = *reinterpret_cast<const float4*>(Ww + (size_t)br[i] * E_ + bc[i]);
                pre = true;
            }
        }

        // ---- tile weighted partial: sum_r w_r * A[r,:], A from hot L2 ----
        {
            int e4 = tid & 127, sg = tid >> 7;  // 4 row-groups x 128 cols
            const float* Abase = Ab + e4 * 4;
            float4 pacc = make_float4(0.f, 0.f, 0.f, 0.f);
#pragma unroll 4
            for (int r = sg; r < nv; r += 4) {
                float w = wrow[r];
                float4 a = *reinterpret_cast<const float4*>(Abase + (size_t)r * E_);
                pacc.x += w * a.x;
                pacc.y += w * a.y;
                pacc.z += w * a.z;
                pacc.w += w * a.w;
            }
            float4* red4 = reinterpret_cast<float4*>(smc);  // 8KB; GEMM bufs free
            red4[sg * 128 + e4] = pacc;
            __syncthreads();
            if (sg == 0) {
                float4 s0v = red4[e4];
                float4 s1v = red4[128 + e4];
                float4 s2v = red4[256 + e4];
                float4 s3v = red4[384 + e4];
                s0v.x += s1v.x + s2v.x + s3v.x;
                s0v.y += s1v.y + s2v.y + s3v.y;
                s0v.z += s1v.z + s2v.z + s3v.z;
                s0v.w += s1v.w + s2v.w + s3v.w;
                g_tpart4[(size_t)(b * 16 + tile) * 128 + e4] = s0v;
            }
        }

        // ---- batch done-counter; last valid tile combines the batch ----
        __threadfence();  // release our partial/stats/scores
        __syncthreads();
        if (tid == 0) s_old = atomicAdd(&g_bdone[b], 1u);
        __syncthreads();
        int ntl = (len + 127) >> 7;  // valid tiles for this batch (>=1)
        if (s_old + 1 == (unsigned)ntl) {
            __threadfence();  // acquire all tiles' writes
            if (tid < 32) {
                float m = (tid < ntl) ? g_mt[b * 16 + tid] : -1e30f;
#pragma unroll
                for (int o = 16; o > 0; o >>= 1)
                    m = fmaxf(m, __shfl_xor_sync(0xffffffffu, m, o));
                if (tid == 0) sM = m;
            }
            __syncthreads();
            float M = sM;
            if (tid < 32) {
                float e = (tid < ntl) ? __expf(g_mt[b * 16 + tid] - M) : 0.0f;
                if (tid < 16) sE[tid] = e;
                float l = (tid < ntl) ? e * g_lt[b * 16 + tid] : 0.0f;
#pragma unroll
                for (int o = 16; o > 0; o >>= 1) l += __shfl_xor_sync(0xffffffffu, l, o);
                if (tid == 0) sInv = __fdividef(1.0f, l);  // 1e-10 term <= 1e-10 rel
            }
            __syncthreads();
            float inv = sInv;
            const float* gp = reinterpret_cast<const float*>(g_tpart4);
            float f = 0.0f;
            for (int tt = 0; tt < ntl; tt++)
                f += sE[tt] * gp[(size_t)(b * 16 + tt) * E_ + tid];
            feat[b * E_ + tid] = f * inv;
            if (attn_out) {
                const float* sc = g_scores + (size_t)b * S_;
#pragma unroll
                for (int i = 0; i < 4; i++) {
                    int s = tid + i * 512;
                    attn_out[(size_t)b * S_ + s] =
                        (s < len) ? __expf(sc[s] - M) * inv : 0.0f;
                }
            }
        }
        __syncthreads();  // smem (sE/sM/red4/wrow) quiesced before next ticket
        t = tn;
    }

    // ---- self-reset: last CTA out restores counters for next graph replay ----
    __syncthreads();
    if (tid == 0) {
        __threadfence();
        unsigned d = atomicAdd(&g_done, 1u);
        if (d == (unsigned)(gridDim.x - 1)) {
            g_ticket = 0u;
            g_ctx_done = 0u;
            g_done = 0u;
            for (int i = 0; i < B_; i++) g_bdone[i] = 0u;
            __threadfence();
        }
    }
}

// ---------------------------------------------------------------------------
extern "C" void kernel_launch(void* const* d_in, const int* in_sizes, int n_in,
                              void* d_out, int out_size) {
    const float* A        = (const float*)d_in[0];
    const int*   lengths  = (const int*)d_in[1];
    const float* context  = (const float*)d_in[2];
    const float* W_word   = (const float*)d_in[3];
    const float* b_word   = (const float*)d_in[4];
    const float* W_ctx    = (const float*)d_in[5];
    const float* b_ctx    = (const float*)d_in[6];
    const float* w_hidden = (const float*)d_in[7];

    float* out = (float*)d_out;
    float* feat_out = out;
    float* attn_out = (out_size >= B_ * E_ + B_ * S_) ? out + B_ * E_ : nullptr;

    const int SCORES_SMEM = 128 * LDWF * 4 + 2048;  // 69632
    cudaFuncSetAttribute(mega_kernel, cudaFuncAttributeMaxDynamicSharedMemorySize,
                         SCORES_SMEM);

    mega_kernel<<<GRID_CTAS, 512, SCORES_SMEM>>>(A, W_word, lengths, w_hidden,
                                                 context, W_ctx, b_ctx, b_word,
                                                 feat_out, attn_out);
}